// round 6
// baseline (speedup 1.0000x reference)
#include <cuda_runtime.h>
#include <stdint.h>
#include <math.h>

#define NEGV -1e30f
#define NC   4          // chunks per batch
#define TT   128        // threads per sw CTA
#define STEPS 639       // 512 + TT - 1
#define FS   656        // feed rows (>= 80 windows * 8)

// ---- static device scratch ----
__device__ float g_S[4 * 512 * 512];            // score matrices
__device__ float g_n2[2 * 4 * 512];             // row norms
__device__ float g_Sf[4 * NC * FS * 128];       // skewed S feed  [b][c][u][t]
__device__ float g_gof[NC * FS * 128];          // skewed go feed [c][u][t]
__device__ float g_gef[NC * FS * 128];          // skewed ge feed
__device__ float g_Df[4 * NC * FS * 128];       // skewed D output feed
__device__ float4 g_bnd[4 * NC * 520];          // boundary ring {D,Ix,h,k} per row
__device__ int   g_flag[32];                    // progress flags [b*NC+c]
__device__ float g_pm[288], g_ps[288];          // LSE partials

__device__ __forceinline__ float lse2(float a, float b) {
    float m = fmaxf(a, b);
    float n = fminf(a, b);
    return m + __logf(1.0f + __expf(n - m));
}
__device__ __forceinline__ int ld_acq(const int* p) {
    int v;
    asm volatile("ld.acquire.gpu.s32 %0, [%1];" : "=r"(v) : "l"(p) : "memory");
    return v;
}
__device__ __forceinline__ void st_rel(int* p, int v) {
    asm volatile("st.release.gpu.s32 [%0], %1;" :: "l"(p), "r"(v) : "memory");
}
__device__ __forceinline__ void cp16(unsigned int ds, const float* src) {
    asm volatile("cp.async.cg.shared.global [%0], [%1], 16;" :: "r"(ds), "l"(src));
}

// window copy: window v (8 rows x 128 = 1024 floats per array) into buffer p.
// Each thread copies 2 x 16B per array; dst byte offset = chunk * 16.
__device__ __forceinline__ void copy_window(unsigned int feedBase, int t,
                                            const float* a0, const float* a1,
                                            const float* a2, int v, int p) {
    unsigned int db = feedBase + (unsigned int)p * (3u * 1024u * 4u);
    const float* s0 = a0 + v * 1024;
    const float* s1 = a1 + v * 1024;
    const float* s2 = a2 + v * 1024;
    #pragma unroll
    for (int jj = 0; jj < 2; jj++) {
        int rem = t + jj * 128;
        cp16(db + (unsigned int)rem * 16u, s0 + rem * 4);
    }
    #pragma unroll
    for (int jj = 0; jj < 2; jj++) {
        int rem = t + jj * 128;
        cp16(db + 1024u * 4u + (unsigned int)rem * 16u, s1 + rem * 4);
    }
    #pragma unroll
    for (int jj = 0; jj < 2; jj++) {
        int rem = t + jj * 128;
        cp16(db + 2u * 1024u * 4u + (unsigned int)rem * 16u, s2 + rem * 4);
    }
    asm volatile("cp.async.commit_group;");
}

// ================= norms + flag reset =================
__global__ void norm_kernel(const float* __restrict__ x, const float* __restrict__ y) {
    if (blockIdx.x == 0 && threadIdx.x < 32) g_flag[threadIdx.x] = 0;
    int w = (blockIdx.x * blockDim.x + threadIdx.x) >> 5;
    int lane = threadIdx.x & 31;
    #pragma unroll
    for (int s = 0; s < 16; s++) {
        int row = w + s * 256;
        const float* p = (row < 2048) ? (x + row * 128) : (y + (row - 2048) * 128);
        float v0 = p[lane], v1 = p[lane + 32], v2 = p[lane + 64], v3 = p[lane + 96];
        float sum = v0 * v0 + v1 * v1 + v2 * v2 + v3 * v3;
        #pragma unroll
        for (int o = 16; o > 0; o >>= 1) sum += __shfl_xor_sync(0xffffffffu, sum, o);
        if (lane == 0) g_n2[row] = sum;
    }
}

// ================= S = x2 + y2 - 2 x.y  (64x64 tiles) =================
__global__ void __launch_bounds__(256) dist_kernel(const float* __restrict__ x,
                                                   const float* __restrict__ y) {
    int b = blockIdx.z;
    int i0 = blockIdx.y * 64, j0 = blockIdx.x * 64;
    const float* xb = x + (b * 512 + i0) * 128;
    const float* yb = y + (b * 512 + j0) * 128;
    __shared__ float xs[16][64];
    __shared__ float ys[16][64];
    int tid = threadIdx.x;
    int tx = tid & 15, ty = tid >> 4;
    float acc[4][4];
    #pragma unroll
    for (int r = 0; r < 4; r++)
        #pragma unroll
        for (int c = 0; c < 4; c++) acc[r][c] = 0.f;

    for (int kc = 0; kc < 128; kc += 16) {
        __syncthreads();
        #pragma unroll
        for (int l = 0; l < 4; l++) {
            int e = tid + l * 256;
            int r = e >> 4, kk = e & 15;
            xs[kk][r] = xb[r * 128 + kc + kk];
            ys[kk][r] = yb[r * 128 + kc + kk];
        }
        __syncthreads();
        #pragma unroll
        for (int kk = 0; kk < 16; kk++) {
            float4 a  = *(const float4*)&xs[kk][ty * 4];
            float4 bv = *(const float4*)&ys[kk][tx * 4];
            float ar[4] = {a.x, a.y, a.z, a.w};
            float br[4] = {bv.x, bv.y, bv.z, bv.w};
            #pragma unroll
            for (int r = 0; r < 4; r++)
                #pragma unroll
                for (int c = 0; c < 4; c++)
                    acc[r][c] = fmaf(ar[r], br[c], acc[r][c]);
        }
    }
    float x2[4], y2[4];
    #pragma unroll
    for (int r = 0; r < 4; r++) x2[r] = g_n2[b * 512 + i0 + ty * 4 + r];
    #pragma unroll
    for (int c = 0; c < 4; c++) y2[c] = g_n2[2048 + b * 512 + j0 + tx * 4 + c];
    float* Sb = g_S + b * 262144;
    #pragma unroll
    for (int r = 0; r < 4; r++) {
        float4 o;
        o.x = x2[r] + y2[0] - 2.f * acc[r][0];
        o.y = x2[r] + y2[1] - 2.f * acc[r][1];
        o.z = x2[r] + y2[2] - 2.f * acc[r][2];
        o.w = x2[r] + y2[3] - 2.f * acc[r][3];
        *(float4*)&Sb[(i0 + ty * 4 + r) * 512 + j0 + tx * 4] = o;
    }
}

// ================= reskew: matrix [512][512] -> feed [c][u][128] =================
// feed[c][u][t] = M[u - t][c*128 + t]
__global__ void __launch_bounds__(256) reskew_kernel(const float* __restrict__ go,
                                                     const float* __restrict__ ge) {
    int m = blockIdx.y;                 // 0..3 = S batches, 4 = go, 5 = ge
    int c = blockIdx.x / 20;
    int rest = blockIdx.x % 20;
    int h = rest / 10, ub = rest % 10;
    const float* src = (m < 4) ? (g_S + m * 262144) : ((m == 4) ? go : ge);
    float* dstB = (m < 4) ? (g_Sf + m * (NC * FS * 128)) : ((m == 4) ? g_gof : g_gef);
    __shared__ float sm[128 * 64];
    int tid = threadIdx.x;
    int u0 = ub * 64;
    int base = u0 - h * 64 - 63;
    int colbase = c * 128 + h * 64;
    #pragma unroll
    for (int l = 0; l < 32; l++) {
        int e = tid + l * 256;
        int r = e >> 6, col = e & 63;
        int gi = base + r;
        sm[e] = (gi >= 0 && gi < 512) ? src[gi * 512 + colbase + col] : 0.f;
    }
    __syncthreads();
    #pragma unroll
    for (int l = 0; l < 16; l++) {
        int e = tid + l * 256;
        int ur = e >> 6, t = e & 63;
        dstB[(c * FS + u0 + ur) * 128 + h * 64 + t] = sm[(ur + 63 - t) * 64 + t];
    }
}

// ================= wavefront soft-SW; NC chunk-CTAs per batch =================
__global__ void __launch_bounds__(TT) sw_kernel() {
    const int c = blockIdx.x, b = blockIdx.y;
    const int t = threadIdx.x, lane = t & 31, warp = t >> 5;
    const float* Sf  = g_Sf + (b * NC + c) * (FS * 128);
    const float* gof = g_gof + c * (FS * 128);
    const float* gef = g_gef + c * (FS * 128);
    float* Df = g_Df + (b * NC + c) * (FS * 128);
    float4* bndW = g_bnd + (b * NC + c) * 520;
    const float4* bndR = g_bnd + (b * NC + c - 1) * 520;
    int* flagW = &g_flag[b * NC + c];
    int* flagR = &g_flag[b * NC + c - 1];

    __shared__ __align__(16) float feed[2][3][1024];  // [buf][S/go/ge][8 rows x 128]
    __shared__ float4 bnd_sm[2][4];        // t0-private boundary window ring
    __shared__ float sh[2][4][4];          // [parity][warp][D,Ix,h,k]

    if (t < 32) ((float*)sh)[t] = ((t & 3) == 3) ? 0.f : NEGV;

    unsigned int feedBase = (unsigned int)__cvta_generic_to_shared(&feed[0][0][0]);

    copy_window(feedBase, t, Sf, gof, gef, 0, 0);

    // boundary prologue (consumer role)
    float4 p0, p1, p2, p3;             // pending batch (rows for the next window)
    int flagv = 0;
    if (t == 0 && c > 0) {
        int fl = 0;
        do { fl = ld_acq(flagR); } while (fl < 12);
        flagv = fl;
        float4 a0 = bndR[1], a1 = bndR[2], a2 = bndR[3], a3 = bndR[4];
        bnd_sm[0][0] = a0; bnd_sm[0][1] = a1; bnd_sm[0][2] = a2; bnd_sm[0][3] = a3;
        p0 = bndR[5]; p1 = bndR[6]; p2 = bndR[7]; p3 = bndR[8];
    }
    asm volatile("cp.async.wait_group 0;");
    __syncthreads();

    float D = NEGV, Ix = NEGV, Iy = NEGV, h = NEGV, k = 0.f;
    float hs = NEGV, ks = 0.f;

    for (int u = 0; u < STEPS; u++) {
        if ((u & 7) == 0) {                       // feed window boundary
            int v = u >> 3;
            if (v + 1 <= 79) copy_window(feedBase, t, Sf, gof, gef, v + 1, (v + 1) & 1);
            asm volatile("cp.async.wait_group 1;");
            __syncthreads();
        }
        if ((u & 3) == 0 && c > 0 && t == 0) {    // boundary batch machinery
            int m = u >> 2;
            int sl = (m + 1) & 1;
            bnd_sm[sl][0] = p0; bnd_sm[sl][1] = p1;
            bnd_sm[sl][2] = p2; bnd_sm[sl][3] = p3;
            int r0 = 4 * m + 9;
            if (r0 <= 512) {
                int need = 4 * m + 12; if (need > 512) need = 512;
                if (flagv < need) {
                    do { flagv = ld_acq(flagR); } while (flagv < need);
                }
                p0 = bndR[r0];
                if (r0 + 1 <= 512) p1 = bndR[r0 + 1];
                if (r0 + 2 <= 512) p2 = bndR[r0 + 2];
                if (r0 + 3 <= 512) p3 = bndR[r0 + 3];
                flagv = ld_acq(flagR);            // pipelined check for next boundary
            }
        }

        // neighbor exchange
        float nD  = __shfl_up_sync(0xffffffffu, D, 1);
        float nIx = __shfl_up_sync(0xffffffffu, Ix, 1);
        float nh  = __shfl_up_sync(0xffffffffu, h, 1);
        float nk  = __shfl_up_sync(0xffffffffu, k, 1);
        if (lane == 0) {
            if (warp > 0) {
                int p = (u + 1) & 1;
                nD = sh[p][warp - 1][0]; nIx = sh[p][warp - 1][1];
                nh = sh[p][warp - 1][2]; nk = sh[p][warp - 1][3];
            } else if (c == 0) {
                nD = NEGV; nIx = NEGV; nh = NEGV; nk = 0.f;
            } else {
                float4 cu = bnd_sm[(u >> 2) & 1][u & 3];
                nD = cu.x; nIx = cu.y; nh = cu.z; nk = cu.w;
            }
        }

        // feed reads
        int pb = (u >> 3) & 1;
        int fo = (u & 7) * 128 + t;
        float sC  = feed[pb][0][fo];
        float goC = feed[pb][1][fo];
        float geC = feed[pb][2][fo];

        bool act = (u >= t) && (u - t < 512);
        if (act) {
            float ix = lse2(nD - goC, nIx - geC);
            float iy = lse2(h - goC, Iy - geC);
            float d  = sC + lse2(hs, ks);
            D = d; Ix = ix; Iy = iy;
            h = lse2(d, ix);
            k = lse2(iy, 0.f);
            Df[u * 128 + t] = d;
            if (t == TT - 1 && c < NC - 1) {
                int i = u - (TT - 2);             // 1-based row
                bndW[i] = make_float4(d, ix, h, k);
                if (((i & 3) == 0) || i == 512) st_rel(flagW, i);
            }
        }
        hs = nh; ks = nk;
        if (lane == 31) {
            sh[u & 1][warp][0] = D;  sh[u & 1][warp][1] = Ix;
            sh[u & 1][warp][2] = h;  sh[u & 1][warp][3] = k;
        }
        __syncthreads();
    }
}

// ================= LSE over valid D entries (skewed feed) =================
__global__ void lse_part() {
    int bx = blockIdx.x;              // 0..39 : chunk*10 + ublock
    int b = blockIdx.y;
    int cchunk = bx / 10, ub = bx % 10;
    const float* Df = g_Df + (b * NC + cchunk) * (FS * 128) + ub * 64 * 128;
    int tid = threadIdx.x;
    float m = NEGV, s = 0.f;
    #pragma unroll
    for (int l = 0; l < 32; l++) {
        int e = tid + l * 256;
        int ur = e >> 7, tc = e & 127;
        int u = ub * 64 + ur;
        bool valid = (u >= tc) && (u - tc < 512);
        float x = Df[e];
        float d = valid ? x : NEGV;
        float nm = fmaxf(m, d);
        s = s * __expf(m - nm) + __expf(d - nm);
        m = nm;
    }
    __shared__ float sm[256], ss[256];
    sm[tid] = m; ss[tid] = s;
    __syncthreads();
    for (int o = 128; o > 0; o >>= 1) {
        if (tid < o) {
            float m2 = sm[tid + o], s2 = ss[tid + o];
            float nm = fmaxf(sm[tid], m2);
            ss[tid] = ss[tid] * __expf(sm[tid] - nm) + s2 * __expf(m2 - nm);
            sm[tid] = nm;
        }
        __syncthreads();
    }
    if (tid == 0) { g_pm[b * 64 + bx] = sm[0]; g_ps[b * 64 + bx] = ss[0]; }
}

__global__ void lse_final(float* __restrict__ out) {
    int t = threadIdx.x;              // 256
    int b = t >> 6, r = t & 63;
    float m = (r < 40) ? g_pm[b * 64 + r] : NEGV;
    float s = (r < 40) ? g_ps[b * 64 + r] : 0.f;
    __shared__ float sm[256], ss[256], vv[4];
    sm[t] = m; ss[t] = s;
    __syncthreads();
    if (r < 8) {
        float m2 = sm[t + 32], s2 = ss[t + 32];
        float nm = fmaxf(sm[t], m2);
        ss[t] = ss[t] * __expf(sm[t] - nm) + s2 * __expf(m2 - nm);
        sm[t] = nm;
    }
    __syncthreads();
    for (int o = 16; o > 0; o >>= 1) {
        if (r < o) {
            float m2 = sm[t + o], s2 = ss[t + o];
            float nm = fmaxf(sm[t], m2);
            ss[t] = ss[t] * __expf(sm[t] - nm) + s2 * __expf(m2 - nm);
            sm[t] = nm;
        }
        __syncthreads();
    }
    if (r == 0) vv[b] = sm[t] + logf(ss[t]);
    __syncthreads();
    if (t == 0) out[0] = 0.25f * (vv[0] + vv[1] + vv[2] + vv[3]);
}

// ================= deskew D feed -> probas =================
__global__ void __launch_bounds__(256) deskew_kernel(float* __restrict__ out) {
    int bx = blockIdx.x;              // 0..63 : c*16 + h*8 + rb
    int b = blockIdx.y;
    int c = bx / 16;
    int rest = bx % 16;
    int h = rest / 8, rb = rest % 8;
    const float* Df = g_Df + (b * NC + c) * (FS * 128);
    __shared__ float sm[128 * 64];
    int tid = threadIdx.x;
    int rbase = rb * 64 + h * 64;
    int tbase = h * 64;
    #pragma unroll
    for (int l = 0; l < 32; l++) {
        int e = tid + l * 256;
        int rr = e >> 6, tc = e & 63;
        sm[e] = Df[(rbase + rr) * 128 + tbase + tc];
    }
    __syncthreads();
    float* ob = out + 1 + b * 262144;
    #pragma unroll
    for (int l = 0; l < 16; l++) {
        int e = tid + l * 256;
        int r = e >> 6, tc = e & 63;
        ob[(rb * 64 + r) * 512 + c * 128 + tbase + tc] = sm[(r + tc) * 64 + tc];
    }
}

// ================= launcher =================
extern "C" void kernel_launch(void* const* d_in, const int* in_sizes, int n_in,
                              void* d_out, int out_size) {
    const float* x  = (const float*)d_in[0];
    const float* y  = (const float*)d_in[1];
    const float* go = (const float*)d_in[2];
    const float* ge = (const float*)d_in[3];
    float* out = (float*)d_out;

    norm_kernel<<<32, 256>>>(x, y);
    dist_kernel<<<dim3(8, 8, 4), 256>>>(x, y);
    reskew_kernel<<<dim3(80, 6), 256>>>(go, ge);
    sw_kernel<<<dim3(NC, 4), TT>>>();
    lse_part<<<dim3(40, 4), 256>>>();
    deskew_kernel<<<dim3(64, 4), 256>>>(out);
    lse_final<<<1, 256>>>(out);
}

// round 7
// speedup vs baseline: 1.7322x; 1.7322x over previous
#include <cuda_runtime.h>
#include <stdint.h>
#include <math.h>

#define NEGV -1e30f
#define SWT  256        // sw threads: 2 cols each
#define STEPS 767       // 512 + 256 - 1
#define FU   768        // feed u-rows (STEPS + 1 prefetch)

// ---- static device scratch ----
__device__ float  g_S[4 * 512 * 512];          // plain score matrices
__device__ float  g_n2[2 * 4 * 512];           // row norms
__device__ float2 g_Sf2[4 * FU * 256];         // skewed S feed   [b][u][t] (cols 2t,2t+1)
__device__ float2 g_gof2[FU * 256];            // skewed go feed
__device__ float2 g_gef2[FU * 256];            // skewed ge feed
__device__ float2 g_Df2[4 * FU * 256];         // skewed D output [b][u][t]
__device__ float  g_pm[256], g_ps[256];        // LSE partials (48 per batch)

__device__ __forceinline__ float lse2(float a, float b) {
    float m = fmaxf(a, b);
    float n = fminf(a, b);
    return m + __logf(1.0f + __expf(n - m));
}

// ================= norms =================
__global__ void norm_kernel(const float* __restrict__ x, const float* __restrict__ y) {
    int w = (blockIdx.x * blockDim.x + threadIdx.x) >> 5;
    int lane = threadIdx.x & 31;
    #pragma unroll
    for (int s = 0; s < 16; s++) {
        int row = w + s * 256;
        const float* p = (row < 2048) ? (x + row * 128) : (y + (row - 2048) * 128);
        float v0 = p[lane], v1 = p[lane + 32], v2 = p[lane + 64], v3 = p[lane + 96];
        float sum = v0 * v0 + v1 * v1 + v2 * v2 + v3 * v3;
        #pragma unroll
        for (int o = 16; o > 0; o >>= 1) sum += __shfl_xor_sync(0xffffffffu, sum, o);
        if (lane == 0) g_n2[row] = sum;
    }
}

// ================= S = x2 + y2 - 2 x.y  (64x64 tiles) =================
__global__ void __launch_bounds__(256) dist_kernel(const float* __restrict__ x,
                                                   const float* __restrict__ y) {
    int b = blockIdx.z;
    int i0 = blockIdx.y * 64, j0 = blockIdx.x * 64;
    const float* xb = x + (b * 512 + i0) * 128;
    const float* yb = y + (b * 512 + j0) * 128;
    __shared__ float xs[16][64];
    __shared__ float ys[16][64];
    int tid = threadIdx.x;
    int tx = tid & 15, ty = tid >> 4;
    float acc[4][4];
    #pragma unroll
    for (int r = 0; r < 4; r++)
        #pragma unroll
        for (int c = 0; c < 4; c++) acc[r][c] = 0.f;

    for (int kc = 0; kc < 128; kc += 16) {
        __syncthreads();
        #pragma unroll
        for (int l = 0; l < 4; l++) {
            int e = tid + l * 256;
            int r = e >> 4, kk = e & 15;
            xs[kk][r] = xb[r * 128 + kc + kk];
            ys[kk][r] = yb[r * 128 + kc + kk];
        }
        __syncthreads();
        #pragma unroll
        for (int kk = 0; kk < 16; kk++) {
            float4 a  = *(const float4*)&xs[kk][ty * 4];
            float4 bv = *(const float4*)&ys[kk][tx * 4];
            float ar[4] = {a.x, a.y, a.z, a.w};
            float br[4] = {bv.x, bv.y, bv.z, bv.w};
            #pragma unroll
            for (int r = 0; r < 4; r++)
                #pragma unroll
                for (int c = 0; c < 4; c++)
                    acc[r][c] = fmaf(ar[r], br[c], acc[r][c]);
        }
    }
    float x2[4], y2[4];
    #pragma unroll
    for (int r = 0; r < 4; r++) x2[r] = g_n2[b * 512 + i0 + ty * 4 + r];
    #pragma unroll
    for (int c = 0; c < 4; c++) y2[c] = g_n2[2048 + b * 512 + j0 + tx * 4 + c];
    float* Sb = g_S + b * 262144;
    #pragma unroll
    for (int r = 0; r < 4; r++) {
        float4 o;
        o.x = x2[r] + y2[0] - 2.f * acc[r][0];
        o.y = x2[r] + y2[1] - 2.f * acc[r][1];
        o.z = x2[r] + y2[2] - 2.f * acc[r][2];
        o.w = x2[r] + y2[3] - 2.f * acc[r][3];
        *(float4*)&Sb[(i0 + ty * 4 + r) * 512 + j0 + tx * 4] = o;
    }
}

// ================= reskew: M[512][512] -> F[u][j] = M[u - (j>>1)][j] =================
// 64u x 64j tiles; src rows span 96.
__global__ void __launch_bounds__(256) reskew_kernel(const float* __restrict__ go,
                                                     const float* __restrict__ ge) {
    int m = blockIdx.y;                 // 0..3 = S batches, 4 = go, 5 = ge
    int ut = blockIdx.x >> 3;           // 0..11
    int jt = blockIdx.x & 7;            // 0..7
    const float* src = (m < 4) ? (g_S + m * 262144) : ((m == 4) ? go : ge);
    float* dst = (m < 4) ? (float*)(g_Sf2 + m * (FU * 256)) :
                 ((m == 4) ? (float*)g_gof2 : (float*)g_gef2);
    int u0 = ut * 64, j0 = jt * 64;
    int base = u0 - (j0 >> 1) - 31;     // min src row - 0
    __shared__ float sm[96 * 64];
    int tid = threadIdx.x;
    #pragma unroll
    for (int l = 0; l < 24; l++) {
        int e = tid + l * 256;
        int rr = e >> 6, cc = e & 63;
        int gr = base + rr;
        sm[e] = (gr >= 0 && gr < 512) ? src[gr * 512 + j0 + cc] : 0.f;
    }
    __syncthreads();
    #pragma unroll
    for (int l = 0; l < 16; l++) {
        int e = tid + l * 256;
        int du = e >> 6, dj = e & 63;
        int rr = du - (dj >> 1) + 31;
        dst[(u0 + du) * 512 + j0 + dj] = sm[rr * 64 + dj];
    }
}

// ================= wavefront soft-SW; 1 CTA per batch, 2 cols/thread =================
__global__ void __launch_bounds__(SWT) sw_kernel() {
    const int b = blockIdx.x;
    const int t = threadIdx.x, lane = t & 31, warp = t >> 5;
    const float2* S2  = g_Sf2 + b * (FU * 256);
    const float2* go2 = g_gof2;
    const float2* ge2 = g_gef2;
    float2* Df2 = g_Df2 + b * (FU * 256);

    __shared__ float sh[2][8][4];   // [parity][warp][Bd,BIx,Bh,Bk]
    if (t < 64) ((float*)sh)[t] = ((t & 3) == 3) ? 0.f : NEGV;

    // per-column carried state (previous row of own columns)
    float AIy = NEGV, Ah = NEGV, Ak = 0.f;
    float BIy = NEGV, Bh = NEGV, Bk = 0.f;
    float Bd = NEGV, BIx = NEGV;          // passed to right neighbor
    float hsN = NEGV, ksN = 0.f;          // neighbor stale h,k (diag of cell A)

    float2 sP = S2[t], goP = go2[t], geP = ge2[t];   // prefetch u=0
    __syncthreads();

    for (int u = 0; u < STEPS; u++) {
        float2 sC = sP, goC = goP, geC = geP;
        {   // prefetch u+1 (u+1 <= 767 < FU)
            int idx = (u + 1) * 256 + t;
            sP = S2[idx]; goP = go2[idx]; geP = ge2[idx];
        }
        // fresh neighbor B-col values (its results of superstep u-1)
        float nD  = __shfl_up_sync(0xffffffffu, Bd, 1);
        float nIx = __shfl_up_sync(0xffffffffu, BIx, 1);
        float nh  = __shfl_up_sync(0xffffffffu, Bh, 1);
        float nk  = __shfl_up_sync(0xffffffffu, Bk, 1);
        if (lane == 0) {
            if (warp > 0) {
                int p = (u + 1) & 1;
                nD = sh[p][warp - 1][0]; nIx = sh[p][warp - 1][1];
                nh = sh[p][warp - 1][2]; nk = sh[p][warp - 1][3];
            } else {
                nD = NEGV; nIx = NEGV; nh = NEGV; nk = 0.f;
            }
        }
        bool act = (u >= t) && (u - t < 512);
        if (act) {
            // ---- cell A (col 2t) ----
            float ixA = lse2(nD - goC.x, nIx - geC.x);   // left (fresh neighbor)
            float iyA = lse2(Ah - goC.x, AIy - geC.x);   // up (own prev row)
            float dA  = sC.x + lse2(hsN, ksN);           // diag (stale neighbor)
            float AhS = Ah, AkS = Ak;                    // stale own-A (diag of B)
            Ah = lse2(dA, ixA);
            Ak = lse2(iyA, 0.f);
            AIy = iyA;
            // ---- cell B (col 2t+1) ----
            float ixB = lse2(dA - goC.y, ixA - geC.y);   // left = A current
            float iyB = lse2(Bh - goC.y, BIy - geC.y);   // up (own prev row)
            float dB  = sC.y + lse2(AhS, AkS);           // diag = own A prev row
            Bh = lse2(dB, ixB);
            Bk = lse2(iyB, 0.f);
            BIy = iyB; Bd = dB; BIx = ixB;
            Df2[u * 256 + t] = make_float2(dA, dB);
        }
        hsN = nh; ksN = nk;                              // fresh -> stale
        if (lane == 31) {
            sh[u & 1][warp][0] = Bd;  sh[u & 1][warp][1] = BIx;
            sh[u & 1][warp][2] = Bh;  sh[u & 1][warp][3] = Bk;
        }
        __syncthreads();
    }
}

// ================= LSE over valid D entries (skewed feed) =================
__global__ void lse_part() {
    int blk = blockIdx.x;             // 0..47
    int b = blockIdx.y;
    const float* Df = (const float*)(g_Df2 + b * (FU * 256)) + blk * 8192;
    int ubase = blk * 16;             // 8192 floats = 16 u-rows of 512
    int tid = threadIdx.x;
    float m = NEGV, s = 0.f;
    #pragma unroll
    for (int l = 0; l < 32; l++) {
        int e = tid + l * 256;
        int u = ubase + (e >> 9), j = e & 511;
        int tc = j >> 1;
        bool valid = (u >= tc) && (u - tc < 512);
        float d = valid ? Df[e] : NEGV;
        float nm = fmaxf(m, d);
        s = s * __expf(m - nm) + __expf(d - nm);
        m = nm;
    }
    __shared__ float sm[256], ss[256];
    sm[tid] = m; ss[tid] = s;
    __syncthreads();
    for (int o = 128; o > 0; o >>= 1) {
        if (tid < o) {
            float m2 = sm[tid + o], s2 = ss[tid + o];
            float nm = fmaxf(sm[tid], m2);
            ss[tid] = ss[tid] * __expf(sm[tid] - nm) + s2 * __expf(m2 - nm);
            sm[tid] = nm;
        }
        __syncthreads();
    }
    if (tid == 0) { g_pm[b * 64 + blk] = sm[0]; g_ps[b * 64 + blk] = ss[0]; }
}

__global__ void lse_final(float* __restrict__ out) {
    int t = threadIdx.x;              // 256
    int b = t >> 6, r = t & 63;
    float m = (r < 48) ? g_pm[b * 64 + r] : NEGV;
    float s = (r < 48) ? g_ps[b * 64 + r] : 0.f;
    __shared__ float sm[256], ss[256], vv[4];
    sm[t] = m; ss[t] = s;
    __syncthreads();
    for (int o = 32; o > 0; o >>= 1) {
        if (r < o) {
            float m2 = sm[t + o], s2 = ss[t + o];
            float nm = fmaxf(sm[t], m2);
            ss[t] = ss[t] * __expf(sm[t] - nm) + s2 * __expf(m2 - nm);
            sm[t] = nm;
        }
        __syncthreads();
    }
    if (r == 0) vv[b] = sm[t] + logf(ss[t]);
    __syncthreads();
    if (t == 0) out[0] = 0.25f * (vv[0] + vv[1] + vv[2] + vv[3]);
}

// ================= deskew: probas[r][j] = Df[(r + (j>>1))][j] =================
__global__ void __launch_bounds__(256) deskew_kernel(float* __restrict__ out) {
    int b = blockIdx.y;
    const float* Df = (const float*)(g_Df2 + b * (FU * 256));
    float* ob = out + 1 + b * 262144;
    int idx0 = blockIdx.x * 256 + threadIdx.x;     // 128 blocks x 256 threads
    #pragma unroll
    for (int l = 0; l < 8; l++) {
        int e = idx0 + l * 32768;
        int r = e >> 9, j = e & 511;
        ob[e] = Df[(r + (j >> 1)) * 512 + j];
    }
}

// ================= launcher =================
extern "C" void kernel_launch(void* const* d_in, const int* in_sizes, int n_in,
                              void* d_out, int out_size) {
    const float* x  = (const float*)d_in[0];
    const float* y  = (const float*)d_in[1];
    const float* go = (const float*)d_in[2];
    const float* ge = (const float*)d_in[3];
    float* out = (float*)d_out;

    norm_kernel<<<32, 256>>>(x, y);
    dist_kernel<<<dim3(8, 8, 4), 256>>>(x, y);
    reskew_kernel<<<dim3(96, 6), 256>>>(go, ge);
    sw_kernel<<<4, SWT>>>();
    lse_part<<<dim3(48, 4), 256>>>();
    deskew_kernel<<<dim3(128, 4), 256>>>(out);
    lse_final<<<1, 256>>>(out);
}

// round 8
// speedup vs baseline: 2.1416x; 1.2364x over previous
#include <cuda_runtime.h>
#include <stdint.h>
#include <math.h>

#define NEGV  -1e30f
#define SWT   256         // sw threads: 2 cols x 2 rows per thread-step
#define STEPS 511         // 256 + 255
#define FU    512         // feed u-rows
#define LOG2E 1.4426950408889634f
#define LN2   0.6931471805599453f

// ---- static device scratch ----
__device__ float  g_S[4 * 512 * 512];          // plain score matrices
__device__ float  g_n2[2 * 4 * 512];           // row norms
__device__ float4 g_Sf4[4 * FU * 256];         // skewed S feed (base-2 scaled)
__device__ float4 g_gof4[FU * 256];            // skewed go feed (scaled)
__device__ float4 g_gef4[FU * 256];            // skewed ge feed (scaled)
__device__ float4 g_Df4[4 * FU * 256];         // skewed D output (base-2 domain)
__device__ float  g_pm[256], g_ps[256];        // LSE partials (64 per batch)

__device__ __forceinline__ float ex2a(float x) {
    float r; asm("ex2.approx.ftz.f32 %0, %1;" : "=f"(r) : "f"(x)); return r;
}
__device__ __forceinline__ float lg2a(float x) {
    float r; asm("lg2.approx.ftz.f32 %0, %1;" : "=f"(r) : "f"(x)); return r;
}
// base-2 LSE of two base-2-domain values
__device__ __forceinline__ float lse2b(float a, float b) {
    float m = fmaxf(a, b), n = fminf(a, b);
    return m + lg2a(1.0f + ex2a(n - m));
}

// ================= norms =================
__global__ void norm_kernel(const float* __restrict__ x, const float* __restrict__ y) {
    int w = (blockIdx.x * blockDim.x + threadIdx.x) >> 5;
    int lane = threadIdx.x & 31;
    #pragma unroll
    for (int s = 0; s < 16; s++) {
        int row = w + s * 256;
        const float* p = (row < 2048) ? (x + row * 128) : (y + (row - 2048) * 128);
        float v0 = p[lane], v1 = p[lane + 32], v2 = p[lane + 64], v3 = p[lane + 96];
        float sum = v0 * v0 + v1 * v1 + v2 * v2 + v3 * v3;
        #pragma unroll
        for (int o = 16; o > 0; o >>= 1) sum += __shfl_xor_sync(0xffffffffu, sum, o);
        if (lane == 0) g_n2[row] = sum;
    }
}

// ================= S = x2 + y2 - 2 x.y  (64x64 tiles) =================
__global__ void __launch_bounds__(256) dist_kernel(const float* __restrict__ x,
                                                   const float* __restrict__ y) {
    int b = blockIdx.z;
    int i0 = blockIdx.y * 64, j0 = blockIdx.x * 64;
    const float* xb = x + (b * 512 + i0) * 128;
    const float* yb = y + (b * 512 + j0) * 128;
    __shared__ float xs[16][64];
    __shared__ float ys[16][64];
    int tid = threadIdx.x;
    int tx = tid & 15, ty = tid >> 4;
    float acc[4][4];
    #pragma unroll
    for (int r = 0; r < 4; r++)
        #pragma unroll
        for (int c = 0; c < 4; c++) acc[r][c] = 0.f;

    for (int kc = 0; kc < 128; kc += 16) {
        __syncthreads();
        #pragma unroll
        for (int l = 0; l < 4; l++) {
            int e = tid + l * 256;
            int r = e >> 4, kk = e & 15;
            xs[kk][r] = xb[r * 128 + kc + kk];
            ys[kk][r] = yb[r * 128 + kc + kk];
        }
        __syncthreads();
        #pragma unroll
        for (int kk = 0; kk < 16; kk++) {
            float4 a  = *(const float4*)&xs[kk][ty * 4];
            float4 bv = *(const float4*)&ys[kk][tx * 4];
            float ar[4] = {a.x, a.y, a.z, a.w};
            float br[4] = {bv.x, bv.y, bv.z, bv.w};
            #pragma unroll
            for (int r = 0; r < 4; r++)
                #pragma unroll
                for (int c = 0; c < 4; c++)
                    acc[r][c] = fmaf(ar[r], br[c], acc[r][c]);
        }
    }
    float x2[4], y2[4];
    #pragma unroll
    for (int r = 0; r < 4; r++) x2[r] = g_n2[b * 512 + i0 + ty * 4 + r];
    #pragma unroll
    for (int c = 0; c < 4; c++) y2[c] = g_n2[2048 + b * 512 + j0 + tx * 4 + c];
    float* Sb = g_S + b * 262144;
    #pragma unroll
    for (int r = 0; r < 4; r++) {
        float4 o;
        o.x = x2[r] + y2[0] - 2.f * acc[r][0];
        o.y = x2[r] + y2[1] - 2.f * acc[r][1];
        o.z = x2[r] + y2[2] - 2.f * acc[r][2];
        o.w = x2[r] + y2[3] - 2.f * acc[r][3];
        *(float4*)&Sb[(i0 + ty * 4 + r) * 512 + j0 + tx * 4] = o;
    }
}

// ================= reskew: M[512][512] -> F4[u][t][q], base-2 scaled ============
// F[u][t][q] = LOG2E * M[2(u-t) + (q>>1)][2t + (q&1)]  if 0 <= u-t < 256, else 0
__global__ void __launch_bounds__(256) reskew_kernel(const float* __restrict__ go,
                                                     const float* __restrict__ ge) {
    int m = blockIdx.y;                 // 0..3 = S batches, 4 = go, 5 = ge
    int ut = blockIdx.x >> 3;           // 16 u-tiles of 32
    int jt = blockIdx.x & 7;            // 8 t-tiles of 32
    const float* src = (m < 4) ? (g_S + m * 262144) : ((m == 4) ? go : ge);
    float* dst = (m < 4) ? (float*)(g_Sf4 + m * (FU * 256)) :
                 ((m == 4) ? (float*)g_gof4 : (float*)g_gef4);
    int u0 = ut * 32, t0 = jt * 32;
    int rbase = 2 * (u0 - t0) - 62;     // 126 src rows
    int cbase = 2 * t0;                 // 64 src cols
    __shared__ float sm[126 * 65];
    int tid = threadIdx.x;
    #pragma unroll
    for (int l = 0; l < 32; l++) {
        int e = tid + l * 256;
        if (e < 126 * 64) {
            int rr = e >> 6, cc = e & 63;
            int gr = rbase + rr;
            sm[rr * 65 + cc] = (gr >= 0 && gr < 512) ?
                LOG2E * src[gr * 512 + cbase + cc] : 0.f;
        }
    }
    __syncthreads();
    #pragma unroll
    for (int l = 0; l < 16; l++) {
        int e = tid + l * 256;           // 4096 dst elements
        int q = e & 3, tr = (e >> 2) & 31, ur = e >> 7;
        int u = u0 + ur, t = t0 + tr;
        int dq = u - t;
        float v = 0.f;
        if (dq >= 0 && dq < 256) {
            int rr = 2 * (ur - tr) + (q >> 1) + 62;
            v = sm[rr * 65 + 2 * tr + (q & 1)];
        }
        dst[(u * 256 + t) * 4 + q] = v;
    }
}

// ================= wavefront soft-SW; 1 CTA/batch, 2x2 cells/thread/step ========
__global__ void __launch_bounds__(SWT, 1) sw_kernel() {
    const int b = blockIdx.x;
    const int t = threadIdx.x, lane = t & 31, warp = t >> 5;
    const float4* S4  = g_Sf4 + b * (FU * 256);
    const float4* go4 = g_gof4;
    const float4* ge4 = g_gef4;
    float4* Df4 = g_Df4 + b * (FU * 256);

    __shared__ float sh[2][8][8];   // [parity][warp][Dlo,Ixlo,glo,Dhi,Ixhi,ghi,pad,pad]
    if (t < 128) {
        int q = t & 7;
        ((float*)sh)[t] = (q == 2 || q == 5) ? 0.f : NEGV;
    }

    // carried state (previous superstep's hi row of own columns)
    float hA = NEGV, IyA = NEGV, gA = 0.f;
    float hB = NEGV, IyB = NEGV, gB = 0.f;
    // values passed rightward (own B column, lo & hi rows of last superstep)
    float BDlo = NEGV, BIlo = NEGV, Bglo = 0.f;
    float BDhi = NEGV, BIhi = NEGV, Bghi = 0.f;
    float gstale = 0.f;             // neighbor g at row (ra-1)

    float4 sP = S4[t], goP = go4[t], geP = ge4[t];
    __syncthreads();

    for (int u = 0; u < STEPS; u++) {
        float4 sC = sP, goC = goP, geC = geP;
        {
            int idx = (u + 1) * 256 + t;
            sP = S4[idx]; goP = go4[idx]; geP = ge4[idx];
        }
        // neighbor exchange (neighbor's previous-superstep B-column rows)
        float nDlo = __shfl_up_sync(0xffffffffu, BDlo, 1);
        float nIlo = __shfl_up_sync(0xffffffffu, BIlo, 1);
        float nglo = __shfl_up_sync(0xffffffffu, Bglo, 1);
        float nDhi = __shfl_up_sync(0xffffffffu, BDhi, 1);
        float nIhi = __shfl_up_sync(0xffffffffu, BIhi, 1);
        float nghi = __shfl_up_sync(0xffffffffu, Bghi, 1);
        {   // lane0 fixup: broadcast LDS + select (no divergent branch)
            int p = (u + 1) & 1;
            int wsel = (warp > 0) ? warp - 1 : 0;
            float sD0 = sh[p][wsel][0], sI0 = sh[p][wsel][1], sg0 = sh[p][wsel][2];
            float sD1 = sh[p][wsel][3], sI1 = sh[p][wsel][4], sg1 = sh[p][wsel][5];
            bool l0 = (lane == 0);
            bool w0 = (warp == 0);
            if (l0) {
                nDlo = w0 ? NEGV : sD0;  nIlo = w0 ? NEGV : sI0;  nglo = w0 ? 0.f : sg0;
                nDhi = w0 ? NEGV : sD1;  nIhi = w0 ? NEGV : sI1;  nghi = w0 ? 0.f : sg1;
            }
        }

        bool act = (u >= t) && (u - t < 256);
        if (act) {
            // rows ra = 2(u-t), rb = ra+1; cols ja = 2t, jb = 2t+1
            // cell (ra, ja)
            float ix1 = lse2b(nDlo - goC.x, nIlo - geC.x);
            float iy1 = lse2b(hA - goC.x, IyA - geC.x);
            float d1  = sC.x + gstale;
            float h1  = lse2b(d1, ix1);
            float k1  = lse2b(iy1, 0.f);
            float g1  = lse2b(h1, k1);
            // cell (ra, jb)
            float ix2 = lse2b(d1 - goC.y, ix1 - geC.y);
            float iy2 = lse2b(hB - goC.y, IyB - geC.y);
            float d2  = sC.y + gA;
            float h2  = lse2b(d2, ix2);
            float k2  = lse2b(iy2, 0.f);
            float g2  = lse2b(h2, k2);
            // cell (rb, ja)
            float ix3 = lse2b(nDhi - goC.z, nIhi - geC.z);
            float iy3 = lse2b(h1 - goC.z, iy1 - geC.z);
            float d3  = sC.z + nglo;
            float h3  = lse2b(d3, ix3);
            float k3  = lse2b(iy3, 0.f);
            float g3  = lse2b(h3, k3);
            // cell (rb, jb)
            float ix4 = lse2b(d3 - goC.w, ix3 - geC.w);
            float iy4 = lse2b(h2 - goC.w, iy2 - geC.w);
            float d4  = sC.w + g1;
            float h4  = lse2b(d4, ix4);
            float k4  = lse2b(iy4, 0.f);
            float g4  = lse2b(h4, k4);

            Df4[u * 256 + t] = make_float4(d1, d2, d3, d4);

            hA = h3; IyA = iy3; gA = g3;
            hB = h4; IyB = iy4; gB = g4;
            BDlo = d2; BIlo = ix2; Bglo = g2;
            BDhi = d4; BIhi = ix4; Bghi = g4;
        }
        gstale = nghi;
        if (lane == 31) {
            sh[u & 1][warp][0] = BDlo; sh[u & 1][warp][1] = BIlo; sh[u & 1][warp][2] = Bglo;
            sh[u & 1][warp][3] = BDhi; sh[u & 1][warp][4] = BIhi; sh[u & 1][warp][5] = Bghi;
        }
        __syncthreads();
    }
}

// ================= LSE over valid D slots (base-2 domain) =================
__global__ void lse_part() {
    int blk = blockIdx.x, b = blockIdx.y;    // 64 x 4
    const float4* Dv = g_Df4 + b * (FU * 256);
    int tid = threadIdx.x;
    float m = NEGV, s = 0.f;
    #pragma unroll
    for (int l = 0; l < 8; l++) {
        int slot = blk * 2048 + tid + l * 256;
        int u = slot >> 8, tc = slot & 255;
        int dq = u - tc;
        if (dq >= 0 && dq < 256) {
            float4 v = Dv[slot];
            float m4 = fmaxf(fmaxf(v.x, v.y), fmaxf(v.z, v.w));
            float nm = fmaxf(m, m4);
            s = s * ex2a(m - nm) + ex2a(v.x - nm) + ex2a(v.y - nm)
                                 + ex2a(v.z - nm) + ex2a(v.w - nm);
            m = nm;
        }
    }
    __shared__ float sm[256], ss[256];
    sm[tid] = m; ss[tid] = s;
    __syncthreads();
    for (int o = 128; o > 0; o >>= 1) {
        if (tid < o) {
            float m2 = sm[tid + o], s2 = ss[tid + o];
            float nm = fmaxf(sm[tid], m2);
            ss[tid] = ss[tid] * ex2a(sm[tid] - nm) + s2 * ex2a(m2 - nm);
            sm[tid] = nm;
        }
        __syncthreads();
    }
    if (tid == 0) { g_pm[b * 64 + blk] = sm[0]; g_ps[b * 64 + blk] = ss[0]; }
}

__global__ void lse_final(float* __restrict__ out) {
    int t = threadIdx.x;              // 256
    int b = t >> 6, r = t & 63;
    __shared__ float sm[256], ss[256], vv[4];
    sm[t] = g_pm[b * 64 + r]; ss[t] = g_ps[b * 64 + r];
    __syncthreads();
    for (int o = 32; o > 0; o >>= 1) {
        if (r < o) {
            float m2 = sm[t + o], s2 = ss[t + o];
            float nm = fmaxf(sm[t], m2);
            ss[t] = ss[t] * ex2a(sm[t] - nm) + s2 * ex2a(m2 - nm);
            sm[t] = nm;
        }
        __syncthreads();
    }
    if (r == 0) vv[b] = LN2 * (sm[t] + lg2a(ss[t]));
    __syncthreads();
    if (t == 0) out[0] = 0.25f * (vv[0] + vv[1] + vv[2] + vv[3]);
}

// ================= deskew: probas[r][j] = LN2 * Df4[t+(r>>1)][t=j>>1].q ==========
__global__ void __launch_bounds__(256) deskew_kernel(float* __restrict__ out) {
    int b = blockIdx.y;
    const float* Df = (const float*)(g_Df4 + b * (FU * 256));
    float* ob = out + 1 + b * 262144;
    int e0 = blockIdx.x * 256 + threadIdx.x;     // 128 blocks
    #pragma unroll
    for (int l = 0; l < 8; l++) {
        int e = e0 + l * 32768;
        int r = e >> 9, j = e & 511;
        int tc = j >> 1;
        int u = tc + (r >> 1);
        int q = ((r & 1) << 1) | (j & 1);
        ob[e] = LN2 * Df[(u * 256 + tc) * 4 + q];
    }
}

// ================= launcher =================
extern "C" void kernel_launch(void* const* d_in, const int* in_sizes, int n_in,
                              void* d_out, int out_size) {
    const float* x  = (const float*)d_in[0];
    const float* y  = (const float*)d_in[1];
    const float* go = (const float*)d_in[2];
    const float* ge = (const float*)d_in[3];
    float* out = (float*)d_out;

    norm_kernel<<<32, 256>>>(x, y);
    dist_kernel<<<dim3(8, 8, 4), 256>>>(x, y);
    reskew_kernel<<<dim3(128, 6), 256>>>(go, ge);
    sw_kernel<<<4, SWT>>>();
    lse_part<<<dim3(64, 4), 256>>>();
    deskew_kernel<<<dim3(128, 4), 256>>>(out);
    lse_final<<<1, 256>>>(out);
}